// round 2
// baseline (speedup 1.0000x reference)
#include <cuda_runtime.h>
#include <cuda_bf16.h>

// Problem constants
#define TT 128      // time steps
#define BB 64       // batch
#define EE 512      // embedding dim
#define HH 1024     // hidden dim
#define NG 4096     // 4*H
#define OUT_STRIDE_T 2048          // 2*H per (b,t)
#define OUT_STRIDE_B (TT*2048)     // per-batch stride in output

// ---------------------------------------------------------------------------
// Device scratch (no allocations allowed; static __device__ globals)
// ---------------------------------------------------------------------------
__device__ float g_X[TT*BB*EE];               // x_tbe  [T,B,E]
__device__ float g_Zf[TT*BB*NG];              // layer input projections (reused L0->L1)
__device__ float g_Zb[TT*BB*NG];
__device__ float g_H0f[TT*BB*HH];             // layer-0 hidden history (fwd, natural t)
__device__ float g_H0b[TT*BB*HH];             // layer-0 hidden history (bwd, scan order s)
__device__ float g_Wp_f0[EE*NG];              // gate-permuted weights
__device__ float g_Wp_b0[EE*NG];
__device__ float g_Wp_f1[HH*NG];
__device__ float g_Wp_b1[HH*NG];
__device__ float g_Up_f0[HH*NG];
__device__ float g_Up_b0[HH*NG];
__device__ float g_Up_f1[HH*NG];
__device__ float g_Up_b1[HH*NG];
__device__ float g_c_f0[BB*HH];
__device__ float g_c_b0[BB*HH];
__device__ float g_c_f1[BB*HH];
__device__ float g_c_b1[BB*HH];

// ---------------------------------------------------------------------------
// Embedding gather: X[t][b][e] = emb[tokens[b][t]][e]
// ---------------------------------------------------------------------------
__global__ __launch_bounds__(256) void gather_embed(
    const int* __restrict__ tokens, const float* __restrict__ emb,
    float* __restrict__ X)
{
    long idx = (long)blockIdx.x * 256 + threadIdx.x;
    if (idx >= (long)TT*BB*EE) return;
    int e  = (int)(idx & (EE-1));
    int tb = (int)(idx >> 9);       // E = 512 = 2^9
    int b  = tb & (BB-1);
    int t  = tb >> 6;               // B = 64 = 2^6
    int tok = tokens[b*TT + t];
    X[idx] = emb[(long)tok*EE + e];
}

// ---------------------------------------------------------------------------
// Weight permute: dst[r][j*4+g] = src[r][g*1024+j]  (gate-interleave columns)
// ---------------------------------------------------------------------------
__global__ __launch_bounds__(256) void permute_w(
    const float* __restrict__ src, float* __restrict__ dst, int rows)
{
    int idx = blockIdx.x * 256 + threadIdx.x;
    if (idx >= rows * NG) return;
    int r = idx >> 12;              // NG = 4096 = 2^12
    int p = idx & (NG-1);
    int j = p >> 2;
    int g = p & 3;
    dst[idx] = src[(r << 12) + (g << 10) + j];
}

// ---------------------------------------------------------------------------
// Batched SGEMM with gate-permuted bias epilogue.
//   C[M,4096] = A[M,K] @ B[K,4096] + bias_perm
// Tiling: 128x128 block tile, BK=8, 256 threads, 8x8 micro-tile.
// M, K divisible by tile sizes (8192 x {512,1024}); no bounds checks.
// ---------------------------------------------------------------------------
__global__ __launch_bounds__(256) void sgemm_bias(
    const float* __restrict__ A, const float* __restrict__ B,
    const float* __restrict__ bias, float* __restrict__ C,
    int M, int K)
{
    __shared__ float As[8][128];
    __shared__ float Bs[8][128];

    const int tid  = threadIdx.x;
    const int row0 = blockIdx.y * 128;
    const int col0 = blockIdx.x * 128;
    const int tr   = (tid / 16) * 8;
    const int tc   = (tid % 16) * 8;

    // load index mapping
    const int am  = tid >> 1;          // 0..127
    const int ak  = (tid & 1) * 4;     // 0 or 4
    const int bk  = tid >> 5;          // 0..7
    const int bn  = (tid & 31) * 4;    // 0..124

    float acc[8][8];
    #pragma unroll
    for (int i = 0; i < 8; i++)
        #pragma unroll
        for (int j = 0; j < 8; j++) acc[i][j] = 0.f;

    const float* Arow = A + (long)(row0 + am) * K + ak;
    const float* Brow = B + (long)bk * NG + col0 + bn;

    for (int k0 = 0; k0 < K; k0 += 8) {
        float4 av = *(const float4*)(Arow + k0);
        As[ak+0][am] = av.x; As[ak+1][am] = av.y;
        As[ak+2][am] = av.z; As[ak+3][am] = av.w;
        float4 bv = *(const float4*)(Brow + (long)k0 * NG);
        *(float4*)&Bs[bk][bn] = bv;
        __syncthreads();
        #pragma unroll
        for (int kk = 0; kk < 8; ++kk) {
            float a_[8], b_[8];
            #pragma unroll
            for (int i = 0; i < 8; i++) a_[i] = As[kk][tr + i];
            #pragma unroll
            for (int j = 0; j < 8; j++) b_[j] = Bs[kk][tc + j];
            #pragma unroll
            for (int i = 0; i < 8; i++)
                #pragma unroll
                for (int j = 0; j < 8; j++)
                    acc[i][j] = fmaf(a_[i], b_[j], acc[i][j]);
        }
        __syncthreads();
    }

    #pragma unroll
    for (int i = 0; i < 8; i++) {
        long crow = (long)(row0 + tr + i) * NG;
        #pragma unroll
        for (int j = 0; j < 8; j++) {
            int n = col0 + tc + j;   // permuted column: j*4+g
            C[crow + n] = acc[i][j] + bias[(n & 3) * HH + (n >> 2)];
        }
    }
}

// ---------------------------------------------------------------------------
// One LSTM time step, both directions fused (gridDim.y = 2).
// Computes z = Zin(t) + h_prev @ U (gate-permuted), applies gates, updates c
// in place, writes h to hout (history array or d_out for layer 1).
// Block: 64 batch x 64 z-cols (= 16 h-cols x 4 gates); grid.x = 64 tiles.
// 256 threads, 4x4 micro-tile -> each thread owns 4 batch rows x 1 h-col.
// ---------------------------------------------------------------------------
struct StepArgs {
    const float* Z0;  const float* h0;  const float* U0;  float* c0;  float* ho0;
    const float* Z1;  const float* h1;  const float* U1;  float* c1;  float* ho1;
    int hp_stride;    // row stride (floats) of h_prev
    int ho_stride;    // row stride (floats) of h_out
    int first;        // 1 => h_prev = 0, c_prev = 0
};

__global__ __launch_bounds__(256) void lstm_step(StepArgs a)
{
    const int dir = blockIdx.y;
    const float* Z  = dir ? a.Z1 : a.Z0;
    const float* hp = dir ? a.h1 : a.h0;
    const float* U  = dir ? a.U1 : a.U0;
    float*       c  = dir ? a.c1 : a.c0;
    float*       ho = dir ? a.ho1 : a.ho0;

    const int col0 = blockIdx.x * 64;      // over 4096 permuted z-cols
    const int tid  = threadIdx.x;
    const int tr   = (tid / 16) * 4;       // batch rows
    const int tc   = (tid % 16) * 4;       // z cols (multiple of 4 => one h-col)

    float acc[4][4];
    #pragma unroll
    for (int i = 0; i < 4; i++)
        #pragma unroll
        for (int j = 0; j < 4; j++) acc[i][j] = 0.f;

    if (!a.first) {
        __shared__ float As[16][64];       // [k][b]
        __shared__ float Bs[16][64];       // [k][n]
        const int lb  = tid >> 2;          // batch 0..63
        const int lk4 = (tid & 3) * 4;     // k sub-offset
        const int bk  = tid >> 4;          // 0..15
        const int bn  = (tid & 15) * 4;    // 0..60

        for (int k0 = 0; k0 < HH; k0 += 16) {
            float4 hv = *(const float4*)&hp[(long)lb * a.hp_stride + k0 + lk4];
            As[lk4+0][lb] = hv.x; As[lk4+1][lb] = hv.y;
            As[lk4+2][lb] = hv.z; As[lk4+3][lb] = hv.w;
            float4 uv = *(const float4*)&U[(long)(k0 + bk) * NG + col0 + bn];
            *(float4*)&Bs[bk][bn] = uv;
            __syncthreads();
            #pragma unroll
            for (int kk = 0; kk < 16; ++kk) {
                float av[4], bv[4];
                #pragma unroll
                for (int i = 0; i < 4; i++) av[i] = As[kk][tr + i];
                #pragma unroll
                for (int j = 0; j < 4; j++) bv[j] = Bs[kk][tc + j];
                #pragma unroll
                for (int i = 0; i < 4; i++)
                    #pragma unroll
                    for (int j = 0; j < 4; j++)
                        acc[i][j] = fmaf(av[i], bv[j], acc[i][j]);
            }
            __syncthreads();
        }
    }

    // Gate epilogue: cols (tc..tc+3) = gates (i,f,g,o) of h-col j
    const int j = (col0 + tc) >> 2;
    #pragma unroll
    for (int r = 0; r < 4; ++r) {
        const int b = tr + r;
        const float* zrow = Z + (long)b * NG + col0 + tc;
        float zi = acc[r][0] + zrow[0];
        float zf = acc[r][1] + zrow[1];
        float zg = acc[r][2] + zrow[2];
        float zo = acc[r][3] + zrow[3];
        float cold = a.first ? 0.f : c[b * HH + j];
        float si = 1.f / (1.f + __expf(-zi));
        float sf = 1.f / (1.f + __expf(-zf));
        float so = 1.f / (1.f + __expf(-zo));
        float cn = sf * cold + si * tanhf(zg);
        float hn = so * tanhf(cn);
        c[b * HH + j] = cn;
        ho[(long)b * a.ho_stride + j] = hn;
    }
}

// ---------------------------------------------------------------------------
// Final-state copy: tail of d_out = [h_f0, c_f0, h_f1, c_f1], each [B,H].
// ---------------------------------------------------------------------------
__global__ __launch_bounds__(256) void finalize(
    float* __restrict__ out, const float* __restrict__ h_f0_last,
    const float* __restrict__ c_f0, const float* __restrict__ c_f1)
{
    int idx = blockIdx.x * 256 + threadIdx.x;
    if (idx >= BB * HH) return;
    int b = idx >> 10;
    int j = idx & (HH - 1);
    float* tail = out + (long)BB * TT * OUT_STRIDE_T;
    tail[idx]                = h_f0_last[idx];
    tail[BB*HH + idx]        = c_f0[idx];
    tail[2*BB*HH + idx]      = out[(long)b * OUT_STRIDE_B + 127 * OUT_STRIDE_T + j];
    tail[3*BB*HH + idx]      = c_f1[idx];
}

// ---------------------------------------------------------------------------
// Host launch
// ---------------------------------------------------------------------------
static float* dev_addr(const void* sym) {
    void* p = nullptr;
    cudaGetSymbolAddress(&p, sym);
    return (float*)p;
}

extern "C" void kernel_launch(void* const* d_in, const int* in_sizes, int n_in,
                              void* d_out, int out_size)
{
    (void)in_sizes; (void)n_in; (void)out_size;
    const int*   tokens = (const int*)  d_in[0];
    const float* emb    = (const float*)d_in[1];
    const float* W_f0   = (const float*)d_in[2];
    const float* U_f0   = (const float*)d_in[3];
    const float* b_f0   = (const float*)d_in[4];
    const float* W_f1   = (const float*)d_in[5];
    const float* U_f1   = (const float*)d_in[6];
    const float* b_f1   = (const float*)d_in[7];
    const float* W_b0   = (const float*)d_in[8];
    const float* U_b0   = (const float*)d_in[9];
    const float* b_b0   = (const float*)d_in[10];
    const float* W_b1   = (const float*)d_in[11];
    const float* U_b1   = (const float*)d_in[12];
    const float* b_b1   = (const float*)d_in[13];
    float* out = (float*)d_out;

    // Resolve device-global addresses (host API, not captured; cheap & capture-safe)
    static float *X=nullptr, *Zf, *Zb, *H0f, *H0b,
                 *Wp_f0, *Wp_b0, *Wp_f1, *Wp_b1,
                 *Up_f0, *Up_b0, *Up_f1, *Up_b1,
                 *c_f0, *c_b0, *c_f1, *c_b1;
    if (!X) {
        X   = dev_addr(g_X);   Zf  = dev_addr(g_Zf);  Zb  = dev_addr(g_Zb);
        H0f = dev_addr(g_H0f); H0b = dev_addr(g_H0b);
        Wp_f0 = dev_addr(g_Wp_f0); Wp_b0 = dev_addr(g_Wp_b0);
        Wp_f1 = dev_addr(g_Wp_f1); Wp_b1 = dev_addr(g_Wp_b1);
        Up_f0 = dev_addr(g_Up_f0); Up_b0 = dev_addr(g_Up_b0);
        Up_f1 = dev_addr(g_Up_f1); Up_b1 = dev_addr(g_Up_b1);
        c_f0 = dev_addr(g_c_f0); c_b0 = dev_addr(g_c_b0);
        c_f1 = dev_addr(g_c_f1); c_b1 = dev_addr(g_c_b1);
    }

    // 1) embedding gather
    gather_embed<<<(TT*BB*EE + 255)/256, 256>>>(tokens, emb, X);

    // 2) gate-permute all weight matrices
    permute_w<<<(EE*NG + 255)/256, 256>>>(W_f0, Wp_f0, EE);
    permute_w<<<(EE*NG + 255)/256, 256>>>(W_b0, Wp_b0, EE);
    permute_w<<<(HH*NG + 255)/256, 256>>>(W_f1, Wp_f1, HH);
    permute_w<<<(HH*NG + 255)/256, 256>>>(W_b1, Wp_b1, HH);
    permute_w<<<(HH*NG + 255)/256, 256>>>(U_f0, Up_f0, HH);
    permute_w<<<(HH*NG + 255)/256, 256>>>(U_b0, Up_b0, HH);
    permute_w<<<(HH*NG + 255)/256, 256>>>(U_f1, Up_f1, HH);
    permute_w<<<(HH*NG + 255)/256, 256>>>(U_b1, Up_b1, HH);

    // 3) layer-0 input projections (time-batched)
    {
        dim3 grid(NG/128, (TT*BB)/128);
        sgemm_bias<<<grid, 256>>>(X, Wp_f0, b_f0, Zf, TT*BB, EE);
        sgemm_bias<<<grid, 256>>>(X, Wp_b0, b_b0, Zb, TT*BB, EE);
    }

    // 4) layer-0 scan (fwd + bwd fused per step)
    for (int s = 0; s < TT; ++s) {
        int tb = TT - 1 - s;  // bwd reads reversed time
        StepArgs a;
        a.Z0 = Zf + (long)s  * BB * NG;
        a.Z1 = Zb + (long)tb * BB * NG;
        a.h0 = (s > 0) ? H0f + (long)(s-1) * BB * HH : H0f;
        a.h1 = (s > 0) ? H0b + (long)(s-1) * BB * HH : H0b;
        a.U0 = Up_f0;  a.U1 = Up_b0;
        a.c0 = c_f0;   a.c1 = c_b0;
        a.ho0 = H0f + (long)s * BB * HH;
        a.ho1 = H0b + (long)s * BB * HH;
        a.hp_stride = HH;  a.ho_stride = HH;
        a.first = (s == 0);
        lstm_step<<<dim3(NG/64, 2), 256>>>(a);
    }

    // 5) layer-1 input projections (reuse Zf/Zb)
    {
        dim3 grid(NG/128, (TT*BB)/128);
        sgemm_bias<<<grid, 256>>>(H0f, Wp_f1, b_f1, Zf, TT*BB, HH);
        sgemm_bias<<<grid, 256>>>(H0b, Wp_b1, b_b1, Zb, TT*BB, HH);
    }

    // 6) layer-1 scan; h written directly into d_out [B,T,2H]
    for (int s = 0; s < TT; ++s) {
        int tb = TT - 1 - s;  // bwd output time index
        StepArgs a;
        a.Z0 = Zf + (long)s * BB * NG;
        a.Z1 = Zb + (long)s * BB * NG;
        a.h0 = (s > 0) ? out + (long)(s-1) * OUT_STRIDE_T        : out;
        a.h1 = (s > 0) ? out + (long)(tb+1) * OUT_STRIDE_T + HH  : out;
        a.U0 = Up_f1;  a.U1 = Up_b1;
        a.c0 = c_f1;   a.c1 = c_b1;
        a.ho0 = out + (long)s  * OUT_STRIDE_T;
        a.ho1 = out + (long)tb * OUT_STRIDE_T + HH;
        a.hp_stride = OUT_STRIDE_B;  a.ho_stride = OUT_STRIDE_B;
        a.first = (s == 0);
        lstm_step<<<dim3(NG/64, 2), 256>>>(a);
    }

    // 7) final states tail
    finalize<<<(BB*HH + 255)/256, 256>>>(
        out, H0f + (long)(TT-1) * BB * HH, c_f0, c_f1);
}

// round 4
// speedup vs baseline: 1.5086x; 1.5086x over previous
#include <cuda_runtime.h>
#include <cuda_bf16.h>

// Problem constants
#define TT 128      // time steps
#define BB 64       // batch
#define EE 512      // embedding dim
#define HH 1024     // hidden dim
#define NG 4096     // 4*H
#define OUT_STRIDE_T 2048          // 2*H per (b,t)
#define OUT_STRIDE_B (TT*2048)     // per-batch stride in output

// ---------------------------------------------------------------------------
// Device scratch
// ---------------------------------------------------------------------------
__device__ float g_X[TT*BB*EE];               // x_tbe  [T,B,E]
__device__ float g_Zf[TT*BB*NG];              // input projections (reused L0->L1)
__device__ float g_Zb[TT*BB*NG];
__device__ float g_H0f[TT*BB*HH];             // layer-0 hidden history (fwd)
__device__ float g_H0b[TT*BB*HH];             // layer-0 hidden history (bwd scan order)
__device__ float g_Wp_f0[EE*NG];              // gate-permuted, tf32-rounded weights
__device__ float g_Wp_b0[EE*NG];
__device__ float g_Wp_f1[HH*NG];
__device__ float g_Wp_b1[HH*NG];
__device__ float g_Up_f0[HH*NG];
__device__ float g_Up_b0[HH*NG];
__device__ float g_Up_f1[HH*NG];
__device__ float g_Up_b1[HH*NG];
__device__ float g_c_f0[BB*HH];
__device__ float g_c_b0[BB*HH];
__device__ float g_c_f1[BB*HH];
__device__ float g_c_b1[BB*HH];

// tf32 round-to-nearest helper
__device__ __forceinline__ float f2tf(float x) {
    unsigned r;
    asm("cvt.rna.tf32.f32 %0, %1;" : "=r"(r) : "f"(x));
    return __uint_as_float(r);
}

__device__ __forceinline__ void mma_tf32(
    float& d0, float& d1, float& d2, float& d3,
    float a0, float a1, float a2, float a3, float b0, float b1)
{
    asm volatile(
        "mma.sync.aligned.m16n8k8.row.col.f32.tf32.tf32.f32 "
        "{%0,%1,%2,%3}, {%4,%5,%6,%7}, {%8,%9}, {%0,%1,%2,%3};\n"
        : "+f"(d0), "+f"(d1), "+f"(d2), "+f"(d3)
        : "r"(__float_as_uint(a0)), "r"(__float_as_uint(a1)),
          "r"(__float_as_uint(a2)), "r"(__float_as_uint(a3)),
          "r"(__float_as_uint(b0)), "r"(__float_as_uint(b1)));
}

// Gate permutation: permuted col p <- source col g*1024 + j,
// with g = (p>>3)&3,  j = (p>>5)*8 + (p&7).
// A 32-col span [32m, 32m+32) holds gate g at sub-offset g*8 of h-cols
// j = 8m..8m+7, so one mma warp tile (4 n-tiles of 8) sees all 4 gates of
// its h-columns in the SAME thread lanes -> shuffle-free gate epilogue.
__device__ __forceinline__ int perm_src_col(int p) {
    int g = (p >> 3) & 3;
    int j = ((p >> 5) << 3) | (p & 7);
    return (g << 10) + j;
}

// ---------------------------------------------------------------------------
// Embedding gather: X[t][b][e] = emb[tokens[b][t]][e]
// ---------------------------------------------------------------------------
__global__ __launch_bounds__(256) void gather_embed(
    const int* __restrict__ tokens, const float* __restrict__ emb,
    float* __restrict__ X)
{
    long idx = (long)blockIdx.x * 256 + threadIdx.x;
    if (idx >= (long)TT*BB*EE) return;
    int e  = (int)(idx & (EE-1));
    int tb = (int)(idx >> 9);
    int b  = tb & (BB-1);
    int t  = tb >> 6;
    int tok = tokens[b*TT + t];
    X[idx] = emb[(long)tok*EE + e];
}

// ---------------------------------------------------------------------------
// Weight permute + tf32 round: dst[r][p] = tf32(src[r][perm_src_col(p)])
// ---------------------------------------------------------------------------
__global__ __launch_bounds__(256) void permute_w(
    const float* __restrict__ src, float* __restrict__ dst, int rows)
{
    int idx = blockIdx.x * 256 + threadIdx.x;
    if (idx >= rows * NG) return;
    int r = idx >> 12;
    int p = idx & (NG-1);
    dst[idx] = f2tf(src[(r << 12) + perm_src_col(p)]);
}

// ---------------------------------------------------------------------------
// tf32 tensor-core GEMM with permuted-bias epilogue.
//   C[M,4096] = A[M,K] @ B[K,4096] + bias(perm)
// Block 128x128, BK=16, 256 threads (8 warps, 2m x 4n), warp tile 64x32.
// A rounded to tf32 at smem fill; B pre-rounded.
// ---------------------------------------------------------------------------
__global__ __launch_bounds__(256) void gemm_tf32_bias(
    const float* __restrict__ A, const float* __restrict__ B,
    const float* __restrict__ bias, float* __restrict__ C,
    int M, int K)
{
    __shared__ float As[16][132];
    __shared__ float Bs[16][132];

    const int tid  = threadIdx.x;
    const int lane = tid & 31;
    const int warp = tid >> 5;
    const int mw   = warp & 1;       // 0..1
    const int nw   = warp >> 1;      // 0..3
    const int row0 = blockIdx.y * 128;
    const int col0 = blockIdx.x * 128;
    const int lq   = lane & 3;
    const int lr   = lane >> 2;

    float acc[4][4][4];
    #pragma unroll
    for (int i = 0; i < 4; i++)
        #pragma unroll
        for (int j = 0; j < 4; j++)
            #pragma unroll
            for (int v = 0; v < 4; v++) acc[i][j][v] = 0.f;

    for (int k0 = 0; k0 < K; k0 += 16) {
        // load A tile (transpose + tf32 round): 512 float4
        #pragma unroll
        for (int i = 0; i < 2; i++) {
            int v = tid + 256*i;
            int m = v >> 2;
            int kq = (v & 3) * 4;
            float4 av = *(const float4*)(A + (long)(row0 + m) * K + k0 + kq);
            As[kq+0][m] = f2tf(av.x);
            As[kq+1][m] = f2tf(av.y);
            As[kq+2][m] = f2tf(av.z);
            As[kq+3][m] = f2tf(av.w);
        }
        // load B tile: 512 float4 (already tf32)
        #pragma unroll
        for (int i = 0; i < 2; i++) {
            int v = tid + 256*i;
            int k = v >> 5;
            int n = (v & 31) * 4;
            *(float4*)&Bs[k][n] = *(const float4*)(B + (long)(k0 + k) * NG + col0 + n);
        }
        __syncthreads();

        #pragma unroll
        for (int kk = 0; kk < 16; kk += 8) {
            float a[4][4];
            #pragma unroll
            for (int mt = 0; mt < 4; mt++) {
                int r = mw*64 + mt*16 + lr;
                a[mt][0] = As[kk + lq][r];
                a[mt][1] = As[kk + lq][r + 8];
                a[mt][2] = As[kk + 4 + lq][r];
                a[mt][3] = As[kk + 4 + lq][r + 8];
            }
            #pragma unroll
            for (int nt = 0; nt < 4; nt++) {
                int cb = nw*32 + nt*8 + lr;
                float b0 = Bs[kk + lq][cb];
                float b1 = Bs[kk + 4 + lq][cb];
                #pragma unroll
                for (int mt = 0; mt < 4; mt++)
                    mma_tf32(acc[mt][nt][0], acc[mt][nt][1],
                             acc[mt][nt][2], acc[mt][nt][3],
                             a[mt][0], a[mt][1], a[mt][2], a[mt][3], b0, b1);
            }
        }
        __syncthreads();
    }

    // epilogue with permuted bias
    #pragma unroll
    for (int mt = 0; mt < 4; mt++) {
        int r = row0 + mw*64 + mt*16 + lr;
        #pragma unroll
        for (int nt = 0; nt < 4; nt++) {
            int p0 = col0 + nw*32 + nt*8 + lq*2;
            float bp0 = bias[perm_src_col(p0)];
            float bp1 = bias[perm_src_col(p0 + 1)];
            C[(long)r * NG + p0]           = acc[mt][nt][0] + bp0;
            C[(long)r * NG + p0 + 1]       = acc[mt][nt][1] + bp1;
            C[(long)(r + 8) * NG + p0]     = acc[mt][nt][2] + bp0;
            C[(long)(r + 8) * NG + p0 + 1] = acc[mt][nt][3] + bp1;
        }
    }
}

// ---------------------------------------------------------------------------
// LSTM step, both directions fused (gridDim.y = 2), tf32 tensor cores.
// z = Zin(t) + h_prev @ U (permuted cols), gates fused in epilogue.
// Block: 64 batch x 64 permuted cols; 8 warps (4m x 2n); warp tile 16x32.
// Each warp's 4 n-tiles are the 4 gates of its 8 h-columns -> local epilogue.
// ---------------------------------------------------------------------------
struct StepArgs {
    const float* Z0;  const float* h0;  const float* U0;  float* c0;  float* ho0;
    const float* Z1;  const float* h1;  const float* U1;  float* c1;  float* ho1;
    int hp_stride;
    int ho_stride;
    int first;
};

__global__ __launch_bounds__(256) void lstm_step(StepArgs a)
{
    const int dir = blockIdx.y;
    const float* Z  = dir ? a.Z1 : a.Z0;
    const float* hp = dir ? a.h1 : a.h0;
    const float* U  = dir ? a.U1 : a.U0;
    float*       c  = dir ? a.c1 : a.c0;
    float*       ho = dir ? a.ho1 : a.ho0;

    const int col0 = blockIdx.x * 64;
    const int tid  = threadIdx.x;
    const int lane = tid & 31;
    const int warp = tid >> 5;
    const int mw   = warp & 3;       // m-tile: batch rows mw*16
    const int nw   = warp >> 2;      // 0..1: cols col0 + nw*32
    const int lq   = lane & 3;
    const int lr   = lane >> 2;

    float acc[4][4];                 // [gate(n-tile)][creg]
    #pragma unroll
    for (int g = 0; g < 4; g++)
        #pragma unroll
        for (int v = 0; v < 4; v++) acc[g][v] = 0.f;

    if (!a.first) {
        __shared__ float As[32][68];     // h tile [k][b], tf32-rounded
        __shared__ float Bs[32][68];     // U tile [k][n] (pre-rounded)

        for (int k0 = 0; k0 < HH; k0 += 32) {
            #pragma unroll
            for (int i = 0; i < 2; i++) {
                int v = tid + 256*i;
                int b = v >> 3;
                int kq = (v & 7) * 4;
                float4 hv = *(const float4*)(hp + (long)b * a.hp_stride + k0 + kq);
                As[kq+0][b] = f2tf(hv.x);
                As[kq+1][b] = f2tf(hv.y);
                As[kq+2][b] = f2tf(hv.z);
                As[kq+3][b] = f2tf(hv.w);
            }
            #pragma unroll
            for (int i = 0; i < 2; i++) {
                int v = tid + 256*i;
                int k = v >> 4;
                int n = (v & 15) * 4;
                *(float4*)&Bs[k][n] = *(const float4*)(U + (long)(k0 + k) * NG + col0 + n);
            }
            __syncthreads();

            #pragma unroll
            for (int kk = 0; kk < 32; kk += 8) {
                int r = mw*16 + lr;
                float a0 = As[kk + lq][r];
                float a1 = As[kk + lq][r + 8];
                float a2 = As[kk + 4 + lq][r];
                float a3 = As[kk + 4 + lq][r + 8];
                #pragma unroll
                for (int g = 0; g < 4; g++) {
                    int cb = nw*32 + g*8 + lr;
                    float b0 = Bs[kk + lq][cb];
                    float b1 = Bs[kk + 4 + lq][cb];
                    mma_tf32(acc[g][0], acc[g][1], acc[g][2], acc[g][3],
                             a0, a1, a2, a3, b0, b1);
                }
            }
            __syncthreads();
        }
    }

    // Gate epilogue: thread owns h-cols j = jbase + 2*lq + {0,1},
    // rows b = mw*16 + lr (+8). All 4 gates local in acc[0..3].
    const int jbase = ((col0 >> 5) + nw) * 8;
    #pragma unroll
    for (int r2 = 0; r2 < 2; r2++) {
        const int b = mw*16 + lr + 8*r2;
        const float* zrow = Z + (long)b * NG + col0 + nw*32;
        #pragma unroll
        for (int jj = 0; jj < 2; jj++) {
            const int v  = r2*2 + jj;
            const int zc = 2*lq + jj;
            float zi = acc[0][v] + zrow[zc];
            float zf = acc[1][v] + zrow[8 + zc];
            float zg = acc[2][v] + zrow[16 + zc];
            float zo = acc[3][v] + zrow[24 + zc];
            int j = jbase + zc;
            float cold = a.first ? 0.f : c[b * HH + j];
            float si = 1.f / (1.f + __expf(-zi));
            float sf = 1.f / (1.f + __expf(-zf));
            float so = 1.f / (1.f + __expf(-zo));
            float cn = sf * cold + si * tanhf(zg);
            float hn = so * tanhf(cn);
            c[b * HH + j] = cn;
            ho[(long)b * a.ho_stride + j] = hn;
        }
    }
}

// ---------------------------------------------------------------------------
// Final-state tail: [h_f0, c_f0, h_f1, c_f1], each [B,H].
// ---------------------------------------------------------------------------
__global__ __launch_bounds__(256) void finalize(
    float* __restrict__ out, const float* __restrict__ h_f0_last,
    const float* __restrict__ c_f0, const float* __restrict__ c_f1)
{
    int idx = blockIdx.x * 256 + threadIdx.x;
    if (idx >= BB * HH) return;
    int b = idx >> 10;
    int j = idx & (HH - 1);
    float* tail = out + (long)BB * TT * OUT_STRIDE_T;
    tail[idx]           = h_f0_last[idx];
    tail[BB*HH + idx]   = c_f0[idx];
    tail[2*BB*HH + idx] = out[(long)b * OUT_STRIDE_B + 127 * OUT_STRIDE_T + j];
    tail[3*BB*HH + idx] = c_f1[idx];
}

// ---------------------------------------------------------------------------
// Host launch
// ---------------------------------------------------------------------------
static float* dev_addr(const void* sym) {
    void* p = nullptr;
    cudaGetSymbolAddress(&p, sym);
    return (float*)p;
}

extern "C" void kernel_launch(void* const* d_in, const int* in_sizes, int n_in,
                              void* d_out, int out_size)
{
    (void)in_sizes; (void)n_in; (void)out_size;
    const int*   tokens = (const int*)  d_in[0];
    const float* emb    = (const float*)d_in[1];
    const float* W_f0   = (const float*)d_in[2];
    const float* U_f0   = (const float*)d_in[3];
    const float* b_f0   = (const float*)d_in[4];
    const float* W_f1   = (const float*)d_in[5];
    const float* U_f1   = (const float*)d_in[6];
    const float* b_f1   = (const float*)d_in[7];
    const float* W_b0   = (const float*)d_in[8];
    const float* U_b0   = (const float*)d_in[9];
    const float* b_b0   = (const float*)d_in[10];
    const float* W_b1   = (const float*)d_in[11];
    const float* U_b1   = (const float*)d_in[12];
    const float* b_b1   = (const float*)d_in[13];
    float* out = (float*)d_out;

    static float *X=nullptr, *Zf, *Zb, *H0f, *H0b,
                 *Wp_f0, *Wp_b0, *Wp_f1, *Wp_b1,
                 *Up_f0, *Up_b0, *Up_f1, *Up_b1,
                 *c_f0, *c_b0, *c_f1, *c_b1;
    if (!X) {
        X   = dev_addr(g_X);   Zf  = dev_addr(g_Zf);  Zb  = dev_addr(g_Zb);
        H0f = dev_addr(g_H0f); H0b = dev_addr(g_H0b);
        Wp_f0 = dev_addr(g_Wp_f0); Wp_b0 = dev_addr(g_Wp_b0);
        Wp_f1 = dev_addr(g_Wp_f1); Wp_b1 = dev_addr(g_Wp_b1);
        Up_f0 = dev_addr(g_Up_f0); Up_b0 = dev_addr(g_Up_b0);
        Up_f1 = dev_addr(g_Up_f1); Up_b1 = dev_addr(g_Up_b1);
        c_f0 = dev_addr(g_c_f0); c_b0 = dev_addr(g_c_b0);
        c_f1 = dev_addr(g_c_f1); c_b1 = dev_addr(g_c_b1);
    }

    // 1) embedding gather
    gather_embed<<<(TT*BB*EE + 255)/256, 256>>>(tokens, emb, X);

    // 2) gate-permute + tf32-round all weight matrices
    permute_w<<<(EE*NG + 255)/256, 256>>>(W_f0, Wp_f0, EE);
    permute_w<<<(EE*NG + 255)/256, 256>>>(W_b0, Wp_b0, EE);
    permute_w<<<(HH*NG + 255)/256, 256>>>(W_f1, Wp_f1, HH);
    permute_w<<<(HH*NG + 255)/256, 256>>>(W_b1, Wp_b1, HH);
    permute_w<<<(HH*NG + 255)/256, 256>>>(U_f0, Up_f0, HH);
    permute_w<<<(HH*NG + 255)/256, 256>>>(U_b0, Up_b0, HH);
    permute_w<<<(HH*NG + 255)/256, 256>>>(U_f1, Up_f1, HH);
    permute_w<<<(HH*NG + 255)/256, 256>>>(U_b1, Up_b1, HH);

    // 3) layer-0 input projections
    {
        dim3 grid(NG/128, (TT*BB)/128);
        gemm_tf32_bias<<<grid, 256>>>(X, Wp_f0, b_f0, Zf, TT*BB, EE);
        gemm_tf32_bias<<<grid, 256>>>(X, Wp_b0, b_b0, Zb, TT*BB, EE);
    }

    // 4) layer-0 scan
    for (int s = 0; s < TT; ++s) {
        int tb = TT - 1 - s;
        StepArgs a;
        a.Z0 = Zf + (long)s  * BB * NG;
        a.Z1 = Zb + (long)tb * BB * NG;
        a.h0 = (s > 0) ? H0f + (long)(s-1) * BB * HH : H0f;
        a.h1 = (s > 0) ? H0b + (long)(s-1) * BB * HH : H0b;
        a.U0 = Up_f0;  a.U1 = Up_b0;
        a.c0 = c_f0;   a.c1 = c_b0;
        a.ho0 = H0f + (long)s * BB * HH;
        a.ho1 = H0b + (long)s * BB * HH;
        a.hp_stride = HH;  a.ho_stride = HH;
        a.first = (s == 0);
        lstm_step<<<dim3(NG/64, 2), 256>>>(a);
    }

    // 5) layer-1 input projections
    {
        dim3 grid(NG/128, (TT*BB)/128);
        gemm_tf32_bias<<<grid, 256>>>(H0f, Wp_f1, b_f1, Zf, TT*BB, HH);
        gemm_tf32_bias<<<grid, 256>>>(H0b, Wp_b1, b_b1, Zb, TT*BB, HH);
    }

    // 6) layer-1 scan; h written directly into d_out [B,T,2H]
    for (int s = 0; s < TT; ++s) {
        int tb = TT - 1 - s;
        StepArgs a;
        a.Z0 = Zf + (long)s * BB * NG;
        a.Z1 = Zb + (long)s * BB * NG;
        a.h0 = (s > 0) ? out + (long)(s-1) * OUT_STRIDE_T        : out;
        a.h1 = (s > 0) ? out + (long)(tb+1) * OUT_STRIDE_T + HH  : out;
        a.U0 = Up_f1;  a.U1 = Up_b1;
        a.c0 = c_f1;   a.c1 = c_b1;
        a.ho0 = out + (long)s  * OUT_STRIDE_T;
        a.ho1 = out + (long)tb * OUT_STRIDE_T + HH;
        a.hp_stride = OUT_STRIDE_B;  a.ho_stride = OUT_STRIDE_B;
        a.first = (s == 0);
        lstm_step<<<dim3(NG/64, 2), 256>>>(a);
    }

    // 7) final states tail
    finalize<<<(BB*HH + 255)/256, 256>>>(
        out, H0f + (long)(TT-1) * BB * HH, c_f0, c_f1);
}

// round 5
// speedup vs baseline: 2.1164x; 1.4029x over previous
#include <cuda_runtime.h>
#include <cuda_bf16.h>

// Problem constants
#define TT 128      // time steps
#define BB 64       // batch
#define EE 512      // embedding dim
#define HH 1024     // hidden dim
#define NG 4096     // 4*H
#define OUT_STRIDE_T 2048          // 2*H per (b,t)
#define OUT_STRIDE_B (TT*2048)     // per-batch stride in output
#define NBLK 128    // persistent scan blocks (64 col-tiles x 2 dirs)

// ---------------------------------------------------------------------------
// Device scratch
// ---------------------------------------------------------------------------
__device__ float g_X[TT*BB*EE];
__device__ float g_Zf[TT*BB*NG];
__device__ float g_Zb[TT*BB*NG];
__device__ float g_H0f[TT*BB*HH];
__device__ float g_H0b[TT*BB*HH];
__device__ float g_Wp_f0[EE*NG];
__device__ float g_Wp_b0[EE*NG];
__device__ float g_Wp_f1[HH*NG];
__device__ float g_Wp_b1[HH*NG];
__device__ float g_Up_f0[HH*NG];
__device__ float g_Up_b0[HH*NG];
__device__ float g_Up_f1[HH*NG];
__device__ float g_Up_b1[HH*NG];
__device__ float g_c_f0[BB*HH];
__device__ float g_c_b0[BB*HH];
__device__ float g_c_f1[BB*HH];
__device__ float g_c_b1[BB*HH];
__device__ unsigned g_bar;            // persistent-scan grid barrier counter

// tf32 round-to-nearest helper
__device__ __forceinline__ float f2tf(float x) {
    unsigned r;
    asm("cvt.rna.tf32.f32 %0, %1;" : "=r"(r) : "f"(x));
    return __uint_as_float(r);
}

__device__ __forceinline__ void mma_tf32(
    float& d0, float& d1, float& d2, float& d3,
    float a0, float a1, float a2, float a3, float b0, float b1)
{
    asm volatile(
        "mma.sync.aligned.m16n8k8.row.col.f32.tf32.tf32.f32 "
        "{%0,%1,%2,%3}, {%4,%5,%6,%7}, {%8,%9}, {%0,%1,%2,%3};\n"
        : "+f"(d0), "+f"(d1), "+f"(d2), "+f"(d3)
        : "r"(__float_as_uint(a0)), "r"(__float_as_uint(a1)),
          "r"(__float_as_uint(a2)), "r"(__float_as_uint(a3)),
          "r"(__float_as_uint(b0)), "r"(__float_as_uint(b1)));
}

// Gate permutation: permuted col p <- source col g*1024 + j,
// g = (p>>3)&3,  j = (p>>5)*8 + (p&7).  A 32-col span holds all 4 gates of
// 8 h-columns in matching mma lanes -> shuffle-free gate epilogue.
__device__ __forceinline__ int perm_src_col(int p) {
    int g = (p >> 3) & 3;
    int j = ((p >> 5) << 3) | (p & 7);
    return (g << 10) + j;
}

// ---------------------------------------------------------------------------
// Embedding gather
// ---------------------------------------------------------------------------
__global__ __launch_bounds__(256) void gather_embed(
    const int* __restrict__ tokens, const float* __restrict__ emb,
    float* __restrict__ X)
{
    long idx = (long)blockIdx.x * 256 + threadIdx.x;
    if (idx >= (long)TT*BB*EE) return;
    int e  = (int)(idx & (EE-1));
    int tb = (int)(idx >> 9);
    int b  = tb & (BB-1);
    int t  = tb >> 6;
    int tok = tokens[b*TT + t];
    X[idx] = emb[(long)tok*EE + e];
}

// ---------------------------------------------------------------------------
// Weight permute + tf32 round
// ---------------------------------------------------------------------------
__global__ __launch_bounds__(256) void permute_w(
    const float* __restrict__ src, float* __restrict__ dst, int rows)
{
    int idx = blockIdx.x * 256 + threadIdx.x;
    if (idx >= rows * NG) return;
    int r = idx >> 12;
    int p = idx & (NG-1);
    dst[idx] = f2tf(src[(r << 12) + perm_src_col(p)]);
}

// ---------------------------------------------------------------------------
// tf32 tensor-core GEMM with permuted-bias epilogue (unchanged from R4).
// ---------------------------------------------------------------------------
__global__ __launch_bounds__(256) void gemm_tf32_bias(
    const float* __restrict__ A, const float* __restrict__ B,
    const float* __restrict__ bias, float* __restrict__ C,
    int M, int K)
{
    __shared__ float As[16][132];
    __shared__ float Bs[16][132];

    const int tid  = threadIdx.x;
    const int lane = tid & 31;
    const int warp = tid >> 5;
    const int mw   = warp & 1;
    const int nw   = warp >> 1;
    const int row0 = blockIdx.y * 128;
    const int col0 = blockIdx.x * 128;
    const int lq   = lane & 3;
    const int lr   = lane >> 2;

    float acc[4][4][4];
    #pragma unroll
    for (int i = 0; i < 4; i++)
        #pragma unroll
        for (int j = 0; j < 4; j++)
            #pragma unroll
            for (int v = 0; v < 4; v++) acc[i][j][v] = 0.f;

    for (int k0 = 0; k0 < K; k0 += 16) {
        #pragma unroll
        for (int i = 0; i < 2; i++) {
            int v = tid + 256*i;
            int m = v >> 2;
            int kq = (v & 3) * 4;
            float4 av = *(const float4*)(A + (long)(row0 + m) * K + k0 + kq);
            As[kq+0][m] = f2tf(av.x);
            As[kq+1][m] = f2tf(av.y);
            As[kq+2][m] = f2tf(av.z);
            As[kq+3][m] = f2tf(av.w);
        }
        #pragma unroll
        for (int i = 0; i < 2; i++) {
            int v = tid + 256*i;
            int k = v >> 5;
            int n = (v & 31) * 4;
            *(float4*)&Bs[k][n] = *(const float4*)(B + (long)(k0 + k) * NG + col0 + n);
        }
        __syncthreads();

        #pragma unroll
        for (int kk = 0; kk < 16; kk += 8) {
            float a[4][4];
            #pragma unroll
            for (int mt = 0; mt < 4; mt++) {
                int r = mw*64 + mt*16 + lr;
                a[mt][0] = As[kk + lq][r];
                a[mt][1] = As[kk + lq][r + 8];
                a[mt][2] = As[kk + 4 + lq][r];
                a[mt][3] = As[kk + 4 + lq][r + 8];
            }
            #pragma unroll
            for (int nt = 0; nt < 4; nt++) {
                int cb = nw*32 + nt*8 + lr;
                float b0 = Bs[kk + lq][cb];
                float b1 = Bs[kk + 4 + lq][cb];
                #pragma unroll
                for (int mt = 0; mt < 4; mt++)
                    mma_tf32(acc[mt][nt][0], acc[mt][nt][1],
                             acc[mt][nt][2], acc[mt][nt][3],
                             a[mt][0], a[mt][1], a[mt][2], a[mt][3], b0, b1);
            }
        }
        __syncthreads();
    }

    #pragma unroll
    for (int mt = 0; mt < 4; mt++) {
        int r = row0 + mw*64 + mt*16 + lr;
        #pragma unroll
        for (int nt = 0; nt < 4; nt++) {
            int p0 = col0 + nw*32 + nt*8 + lq*2;
            float bp0 = bias[perm_src_col(p0)];
            float bp1 = bias[perm_src_col(p0 + 1)];
            C[(long)r * NG + p0]           = acc[mt][nt][0] + bp0;
            C[(long)r * NG + p0 + 1]       = acc[mt][nt][1] + bp1;
            C[(long)(r + 8) * NG + p0]     = acc[mt][nt][2] + bp0;
            C[(long)(r + 8) * NG + p0 + 1] = acc[mt][nt][3] + bp1;
        }
    }
}

// ---------------------------------------------------------------------------
// PERSISTENT LSTM scan: one launch runs all 128 time steps of one layer,
// both directions (128 blocks: dir = blk>>6, col tile = blk&63).
// c state lives in registers across steps. Grid barrier between steps.
// Tiling/mapping identical to R4's lstm_step (proven correct).
// ---------------------------------------------------------------------------
struct ScanArgs {
    const float* z[2];     // Z base per dir (step-s slice = z + s*z_ss)
    long  z_ss[2];         // Z scan-step stride (elements, signed)
    float* h[2];           // h base per dir  (step-s slice = h + s*h_ss)
    long  h_ss[2];         // h scan-step stride (signed)
    long  h_bs[2];         // h batch stride
    const float* U[2];     // gate-permuted recurrent weights
    float* c_out[2];       // final cell-state dump [B*H]
};

__global__ __launch_bounds__(256) void lstm_scan(ScanArgs a)
{
    const int blk  = blockIdx.x;
    const int dir  = blk >> 6;
    const int col0 = (blk & 63) * 64;
    const int tid  = threadIdx.x;
    const int lane = tid & 31;
    const int warp = tid >> 5;
    const int mw   = warp & 3;
    const int nw   = warp >> 2;
    const int lq   = lane & 3;
    const int lr   = lane >> 2;

    const float* Zb0 = a.z[dir];
    const long   zss = a.z_ss[dir];
    float*       Hb  = a.h[dir];
    const long   hss = a.h_ss[dir];
    const long   hbs = a.h_bs[dir];
    const float* U   = a.U[dir];

    // per-thread load coordinates (two 128-thread waves each)
    const int ab0 = tid >> 3,          akq0 = (tid & 7) * 4;
    const int ab1 = (tid + 256) >> 3,  akq1 = ((tid + 256) & 7) * 4;
    const int bk0 = tid >> 4,          bn0  = (tid & 15) * 4;
    const int bk1 = (tid + 256) >> 4,  bn1  = ((tid + 256) & 15) * 4;

    __shared__ float As[32][68];
    __shared__ float Bs[32][68];

    // register-resident cell state for this thread's 4 (b,j) pairs
    float creg[4] = {0.f, 0.f, 0.f, 0.f};
    const int jbase = ((col0 >> 5) + nw) * 8;

    for (int s = 0; s < TT; ++s) {
        const float* Z = Zb0 + (long)s * zss;

        float acc[4][4];
        #pragma unroll
        for (int g = 0; g < 4; g++)
            #pragma unroll
            for (int v = 0; v < 4; v++) acc[g][v] = 0.f;

        if (s > 0) {
            const float* hp = Hb + (long)(s - 1) * hss;
            // software pipeline: preload k0=0 tiles into registers
            float4 pa0 = *(const float4*)(hp + (long)ab0 * hbs + akq0);
            float4 pa1 = *(const float4*)(hp + (long)ab1 * hbs + akq1);
            float4 pb0 = *(const float4*)(U + (long)bk0 * NG + col0 + bn0);
            float4 pb1 = *(const float4*)(U + (long)bk1 * NG + col0 + bn1);

            for (int k0 = 0; k0 < HH; k0 += 32) {
                As[akq0+0][ab0] = f2tf(pa0.x);
                As[akq0+1][ab0] = f2tf(pa0.y);
                As[akq0+2][ab0] = f2tf(pa0.z);
                As[akq0+3][ab0] = f2tf(pa0.w);
                As[akq1+0][ab1] = f2tf(pa1.x);
                As[akq1+1][ab1] = f2tf(pa1.y);
                As[akq1+2][ab1] = f2tf(pa1.z);
                As[akq1+3][ab1] = f2tf(pa1.w);
                *(float4*)&Bs[bk0][bn0] = pb0;
                *(float4*)&Bs[bk1][bn1] = pb1;
                __syncthreads();

                if (k0 + 32 < HH) {
                    const int kn = k0 + 32;
                    pa0 = *(const float4*)(hp + (long)ab0 * hbs + kn + akq0);
                    pa1 = *(const float4*)(hp + (long)ab1 * hbs + kn + akq1);
                    pb0 = *(const float4*)(U + (long)(kn + bk0) * NG + col0 + bn0);
                    pb1 = *(const float4*)(U + (long)(kn + bk1) * NG + col0 + bn1);
                }

                #pragma unroll
                for (int kk = 0; kk < 32; kk += 8) {
                    int r = mw*16 + lr;
                    float a0 = As[kk + lq][r];
                    float a1 = As[kk + lq][r + 8];
                    float a2 = As[kk + 4 + lq][r];
                    float a3 = As[kk + 4 + lq][r + 8];
                    #pragma unroll
                    for (int g = 0; g < 4; g++) {
                        int cb = nw*32 + g*8 + lr;
                        float b0 = Bs[kk + lq][cb];
                        float b1 = Bs[kk + 4 + lq][cb];
                        mma_tf32(acc[g][0], acc[g][1], acc[g][2], acc[g][3],
                                 a0, a1, a2, a3, b0, b1);
                    }
                }
                __syncthreads();
            }
        }

        // Gate epilogue; c in registers; h written to history/output
        float* ho = Hb + (long)s * hss;
        #pragma unroll
        for (int r2 = 0; r2 < 2; r2++) {
            const int b = mw*16 + lr + 8*r2;
            const float* zrow = Z + (long)b * NG + col0 + nw*32;
            #pragma unroll
            for (int jj = 0; jj < 2; jj++) {
                const int v  = r2*2 + jj;
                const int zc = 2*lq + jj;
                float zi = acc[0][v] + zrow[zc];
                float zf = acc[1][v] + zrow[8 + zc];
                float zg = acc[2][v] + zrow[16 + zc];
                float zo = acc[3][v] + zrow[24 + zc];
                float si = 1.f / (1.f + __expf(-zi));
                float sf = 1.f / (1.f + __expf(-zf));
                float so = 1.f / (1.f + __expf(-zo));
                float cn = sf * creg[v] + si * tanhf(zg);
                float hn = so * tanhf(cn);
                creg[v] = cn;
                ho[(long)b * hbs + (jbase + zc)] = hn;
            }
        }

        // -------- grid barrier (release h(s) to all blocks) --------
        __threadfence();
        __syncthreads();
        if (tid == 0) {
            atomicAdd(&g_bar, 1u);
            const unsigned target = (unsigned)(s + 1) * NBLK;
            volatile unsigned* vb = &g_bar;
            while (*vb < target) { }
        }
        __syncthreads();
    }

    // dump final cell state
    float* cdst = a.c_out[dir];
    #pragma unroll
    for (int r2 = 0; r2 < 2; r2++) {
        const int b = mw*16 + lr + 8*r2;
        #pragma unroll
        for (int jj = 0; jj < 2; jj++) {
            const int v  = r2*2 + jj;
            const int zc = 2*lq + jj;
            cdst[b * HH + (jbase + zc)] = creg[v];
        }
    }
}

// ---------------------------------------------------------------------------
// Final-state tail: [h_f0, c_f0, h_f1, c_f1], each [B,H].
// ---------------------------------------------------------------------------
__global__ __launch_bounds__(256) void finalize(
    float* __restrict__ out, const float* __restrict__ h_f0_last,
    const float* __restrict__ c_f0, const float* __restrict__ c_f1)
{
    int idx = blockIdx.x * 256 + threadIdx.x;
    if (idx >= BB * HH) return;
    int b = idx >> 10;
    int j = idx & (HH - 1);
    float* tail = out + (long)BB * TT * OUT_STRIDE_T;
    tail[idx]           = h_f0_last[idx];
    tail[BB*HH + idx]   = c_f0[idx];
    tail[2*BB*HH + idx] = out[(long)b * OUT_STRIDE_B + 127 * OUT_STRIDE_T + j];
    tail[3*BB*HH + idx] = c_f1[idx];
}

// ---------------------------------------------------------------------------
// Host launch
// ---------------------------------------------------------------------------
static float* dev_addr(const void* sym) {
    void* p = nullptr;
    cudaGetSymbolAddress(&p, sym);
    return (float*)p;
}

extern "C" void kernel_launch(void* const* d_in, const int* in_sizes, int n_in,
                              void* d_out, int out_size)
{
    (void)in_sizes; (void)n_in; (void)out_size;
    const int*   tokens = (const int*)  d_in[0];
    const float* emb    = (const float*)d_in[1];
    const float* W_f0   = (const float*)d_in[2];
    const float* U_f0   = (const float*)d_in[3];
    const float* b_f0   = (const float*)d_in[4];
    const float* W_f1   = (const float*)d_in[5];
    const float* U_f1   = (const float*)d_in[6];
    const float* b_f1   = (const float*)d_in[7];
    const float* W_b0   = (const float*)d_in[8];
    const float* U_b0   = (const float*)d_in[9];
    const float* b_b0   = (const float*)d_in[10];
    const float* W_b1   = (const float*)d_in[11];
    const float* U_b1   = (const float*)d_in[12];
    const float* b_b1   = (const float*)d_in[13];
    float* out = (float*)d_out;

    static float *X=nullptr, *Zf, *Zb, *H0f, *H0b,
                 *Wp_f0, *Wp_b0, *Wp_f1, *Wp_b1,
                 *Up_f0, *Up_b0, *Up_f1, *Up_b1,
                 *c_f0, *c_b0, *c_f1, *c_b1;
    static void* bar_addr = nullptr;
    if (!X) {
        X   = dev_addr(g_X);   Zf  = dev_addr(g_Zf);  Zb  = dev_addr(g_Zb);
        H0f = dev_addr(g_H0f); H0b = dev_addr(g_H0b);
        Wp_f0 = dev_addr(g_Wp_f0); Wp_b0 = dev_addr(g_Wp_b0);
        Wp_f1 = dev_addr(g_Wp_f1); Wp_b1 = dev_addr(g_Wp_b1);
        Up_f0 = dev_addr(g_Up_f0); Up_b0 = dev_addr(g_Up_b0);
        Up_f1 = dev_addr(g_Up_f1); Up_b1 = dev_addr(g_Up_b1);
        c_f0 = dev_addr(g_c_f0); c_b0 = dev_addr(g_c_b0);
        c_f1 = dev_addr(g_c_f1); c_b1 = dev_addr(g_c_b1);
        cudaGetSymbolAddress(&bar_addr, g_bar);
    }

    // 1) embedding gather
    gather_embed<<<(TT*BB*EE + 255)/256, 256>>>(tokens, emb, X);

    // 2) gate-permute + tf32-round weights
    permute_w<<<(EE*NG + 255)/256, 256>>>(W_f0, Wp_f0, EE);
    permute_w<<<(EE*NG + 255)/256, 256>>>(W_b0, Wp_b0, EE);
    permute_w<<<(HH*NG + 255)/256, 256>>>(W_f1, Wp_f1, HH);
    permute_w<<<(HH*NG + 255)/256, 256>>>(W_b1, Wp_b1, HH);
    permute_w<<<(HH*NG + 255)/256, 256>>>(U_f0, Up_f0, HH);
    permute_w<<<(HH*NG + 255)/256, 256>>>(U_b0, Up_b0, HH);
    permute_w<<<(HH*NG + 255)/256, 256>>>(U_f1, Up_f1, HH);
    permute_w<<<(HH*NG + 255)/256, 256>>>(U_b1, Up_b1, HH);

    // 3) layer-0 input projections
    {
        dim3 grid(NG/128, (TT*BB)/128);
        gemm_tf32_bias<<<grid, 256>>>(X, Wp_f0, b_f0, Zf, TT*BB, EE);
        gemm_tf32_bias<<<grid, 256>>>(X, Wp_b0, b_b0, Zb, TT*BB, EE);
    }

    // 4) layer-0 persistent scan
    {
        cudaMemsetAsync(bar_addr, 0, sizeof(unsigned));
        ScanArgs a;
        a.z[0] = Zf;                        a.z_ss[0] = (long)BB * NG;
        a.z[1] = Zb + 127L * BB * NG;       a.z_ss[1] = -(long)BB * NG;
        a.h[0] = H0f;  a.h_ss[0] = (long)BB * HH;  a.h_bs[0] = HH;
        a.h[1] = H0b;  a.h_ss[1] = (long)BB * HH;  a.h_bs[1] = HH;
        a.U[0] = Up_f0;  a.U[1] = Up_b0;
        a.c_out[0] = c_f0;  a.c_out[1] = c_b0;
        lstm_scan<<<NBLK, 256>>>(a);
    }

    // 5) layer-1 input projections
    {
        dim3 grid(NG/128, (TT*BB)/128);
        gemm_tf32_bias<<<grid, 256>>>(H0f, Wp_f1, b_f1, Zf, TT*BB, HH);
        gemm_tf32_bias<<<grid, 256>>>(H0b, Wp_b1, b_b1, Zb, TT*BB, HH);
    }

    // 6) layer-1 persistent scan; h written directly into d_out [B,T,2H]
    {
        cudaMemsetAsync(bar_addr, 0, sizeof(unsigned));
        ScanArgs a;
        a.z[0] = Zf;  a.z_ss[0] = (long)BB * NG;
        a.z[1] = Zb;  a.z_ss[1] = (long)BB * NG;   // L1 bwd Z already in scan order
        a.h[0] = out;                       a.h_ss[0] = OUT_STRIDE_T;
        a.h[1] = out + 127L*OUT_STRIDE_T + HH;  a.h_ss[1] = -(long)OUT_STRIDE_T;
        a.h_bs[0] = OUT_STRIDE_B;  a.h_bs[1] = OUT_STRIDE_B;
        a.U[0] = Up_f1;  a.U[1] = Up_b1;
        a.c_out[0] = c_f1;  a.c_out[1] = c_b1;
        lstm_scan<<<NBLK, 256>>>(a);
    }

    // 7) final states tail
    finalize<<<(BB*HH + 255)/256, 256>>>(
        out, H0f + (long)(TT-1) * BB * HH, c_f0, c_f1);
}

// round 7
// speedup vs baseline: 2.4472x; 1.1563x over previous
#include <cuda_runtime.h>
#include <cuda_bf16.h>
#include <cstdint>

// Problem constants
#define TT 128      // time steps
#define BB 64       // batch
#define EE 512      // embedding dim
#define HH 1024     // hidden dim
#define NG 4096     // 4*H
#define HB (HH*BB)
#define OUT_STRIDE_T 2048          // 2*H per (b,t)
#define OUT_STRIDE_B (TT*2048)     // per-batch stride in output
#define NBLK 128    // persistent scan blocks (64 col-tiles x 2 dirs)

// ---------------------------------------------------------------------------
// Device scratch
// ---------------------------------------------------------------------------
__device__ float g_X[TT*BB*EE];
__device__ float g_Zf[TT*BB*NG];
__device__ float g_Zb[TT*BB*NG];
__device__ float g_H0f[TT*BB*HH];
__device__ float g_H0b[TT*BB*HH];
__device__ float g_hT[2*2*HB];        // [dir][pingpong][j][b], tf32-rounded h
__device__ float g_Wp_f0[EE*NG];
__device__ float g_Wp_b0[EE*NG];
__device__ float g_Wp_f1[HH*NG];
__device__ float g_Wp_b1[HH*NG];
__device__ float g_Up_f0[HH*NG];
__device__ float g_Up_b0[HH*NG];
__device__ float g_Up_f1[HH*NG];
__device__ float g_Up_b1[HH*NG];
__device__ float g_c_f0[BB*HH];
__device__ float g_c_b0[BB*HH];
__device__ float g_c_f1[BB*HH];
__device__ float g_c_b1[BB*HH];
__device__ unsigned g_bar;            // persistent-scan grid barrier counter

// tf32 round-to-nearest helper
__device__ __forceinline__ float f2tf(float x) {
    unsigned r;
    asm("cvt.rna.tf32.f32 %0, %1;" : "=r"(r) : "f"(x));
    return __uint_as_float(r);
}

__device__ __forceinline__ void mma_tf32(
    float& d0, float& d1, float& d2, float& d3,
    float a0, float a1, float a2, float a3, float b0, float b1)
{
    asm volatile(
        "mma.sync.aligned.m16n8k8.row.col.f32.tf32.tf32.f32 "
        "{%0,%1,%2,%3}, {%4,%5,%6,%7}, {%8,%9}, {%0,%1,%2,%3};\n"
        : "+f"(d0), "+f"(d1), "+f"(d2), "+f"(d3)
        : "r"(__float_as_uint(a0)), "r"(__float_as_uint(a1)),
          "r"(__float_as_uint(a2)), "r"(__float_as_uint(a3)),
          "r"(__float_as_uint(b0)), "r"(__float_as_uint(b1)));
}

// cp.async helpers (16B, L1-bypass)
__device__ __forceinline__ void cp16(uint32_t dst, const void* src) {
    asm volatile("cp.async.cg.shared.global [%0], [%1], 16;" :: "r"(dst), "l"(src));
}
__device__ __forceinline__ void cp_commit() {
    asm volatile("cp.async.commit_group;");
}
__device__ __forceinline__ void cp_wait0() {
    asm volatile("cp.async.wait_group 0;");
}

// Gate permutation: permuted col p <- source col g*1024 + j,
// g = (p>>3)&3,  j = (p>>5)*8 + (p&7).
__device__ __forceinline__ int perm_src_col(int p) {
    int g = (p >> 3) & 3;
    int j = ((p >> 5) << 3) | (p & 7);
    return (g << 10) + j;
}

// ---------------------------------------------------------------------------
// Embedding gather
// ---------------------------------------------------------------------------
__global__ __launch_bounds__(256) void gather_embed(
    const int* __restrict__ tokens, const float* __restrict__ emb,
    float* __restrict__ X)
{
    long idx = (long)blockIdx.x * 256 + threadIdx.x;
    if (idx >= (long)TT*BB*EE) return;
    int e  = (int)(idx & (EE-1));
    int tb = (int)(idx >> 9);
    int b  = tb & (BB-1);
    int t  = tb >> 6;
    int tok = tokens[b*TT + t];
    X[idx] = emb[(long)tok*EE + e];
}

// ---------------------------------------------------------------------------
// Weight permute + tf32 round
// ---------------------------------------------------------------------------
__global__ __launch_bounds__(256) void permute_w(
    const float* __restrict__ src, float* __restrict__ dst, int rows)
{
    int idx = blockIdx.x * 256 + threadIdx.x;
    if (idx >= rows * NG) return;
    int r = idx >> 12;
    int p = idx & (NG-1);
    dst[idx] = f2tf(src[(r << 12) + perm_src_col(p)]);
}

// ---------------------------------------------------------------------------
// tf32 tensor-core GEMM with permuted-bias epilogue (unchanged, proven).
// ---------------------------------------------------------------------------
__global__ __launch_bounds__(256) void gemm_tf32_bias(
    const float* __restrict__ A, const float* __restrict__ B,
    const float* __restrict__ bias, float* __restrict__ C,
    int M, int K)
{
    __shared__ float As[16][132];
    __shared__ float Bs[16][132];

    const int tid  = threadIdx.x;
    const int lane = tid & 31;
    const int warp = tid >> 5;
    const int mw   = warp & 1;
    const int nw   = warp >> 1;
    const int row0 = blockIdx.y * 128;
    const int col0 = blockIdx.x * 128;
    const int lq   = lane & 3;
    const int lr   = lane >> 2;

    float acc[4][4][4];
    #pragma unroll
    for (int i = 0; i < 4; i++)
        #pragma unroll
        for (int j = 0; j < 4; j++)
            #pragma unroll
            for (int v = 0; v < 4; v++) acc[i][j][v] = 0.f;

    for (int k0 = 0; k0 < K; k0 += 16) {
        #pragma unroll
        for (int i = 0; i < 2; i++) {
            int v = tid + 256*i;
            int m = v >> 2;
            int kq = (v & 3) * 4;
            float4 av = *(const float4*)(A + (long)(row0 + m) * K + k0 + kq);
            As[kq+0][m] = f2tf(av.x);
            As[kq+1][m] = f2tf(av.y);
            As[kq+2][m] = f2tf(av.z);
            As[kq+3][m] = f2tf(av.w);
        }
        #pragma unroll
        for (int i = 0; i < 2; i++) {
            int v = tid + 256*i;
            int k = v >> 5;
            int n = (v & 31) * 4;
            *(float4*)&Bs[k][n] = *(const float4*)(B + (long)(k0 + k) * NG + col0 + n);
        }
        __syncthreads();

        #pragma unroll
        for (int kk = 0; kk < 16; kk += 8) {
            float a[4][4];
            #pragma unroll
            for (int mt = 0; mt < 4; mt++) {
                int r = mw*64 + mt*16 + lr;
                a[mt][0] = As[kk + lq][r];
                a[mt][1] = As[kk + lq][r + 8];
                a[mt][2] = As[kk + 4 + lq][r];
                a[mt][3] = As[kk + 4 + lq][r + 8];
            }
            #pragma unroll
            for (int nt = 0; nt < 4; nt++) {
                int cb = nw*32 + nt*8 + lr;
                float b0 = Bs[kk + lq][cb];
                float b1 = Bs[kk + 4 + lq][cb];
                #pragma unroll
                for (int mt = 0; mt < 4; mt++)
                    mma_tf32(acc[mt][nt][0], acc[mt][nt][1],
                             acc[mt][nt][2], acc[mt][nt][3],
                             a[mt][0], a[mt][1], a[mt][2], a[mt][3], b0, b1);
            }
        }
        __syncthreads();
    }

    #pragma unroll
    for (int mt = 0; mt < 4; mt++) {
        int r = row0 + mw*64 + mt*16 + lr;
        #pragma unroll
        for (int nt = 0; nt < 4; nt++) {
            int p0 = col0 + nw*32 + nt*8 + lq*2;
            float bp0 = bias[perm_src_col(p0)];
            float bp1 = bias[perm_src_col(p0 + 1)];
            C[(long)r * NG + p0]           = acc[mt][nt][0] + bp0;
            C[(long)r * NG + p0 + 1]       = acc[mt][nt][1] + bp1;
            C[(long)(r + 8) * NG + p0]     = acc[mt][nt][2] + bp0;
            C[(long)(r + 8) * NG + p0 + 1] = acc[mt][nt][3] + bp1;
        }
    }
}

// ---------------------------------------------------------------------------
// PERSISTENT LSTM scan, cp.async double-buffered.
// A operand comes from transposed pre-rounded h_T[j][b] (ping-pong) -> the
// A tile is a contiguous copy (no transpose STS, no cvt at fill).
// One __syncthreads per 32-K chunk; copy(k+1) overlaps mma(k).
// ---------------------------------------------------------------------------
struct ScanArgs {
    const float* z[2];     // Z base per dir (step-s slice = z + s*z_ss)
    long  z_ss[2];         // Z scan-step stride (elements, signed)
    float* h[2];           // h base per dir  (step-s slice = h + s*h_ss)
    long  h_ss[2];         // h scan-step stride (signed)
    long  h_bs[2];         // h batch stride
    const float* U[2];     // gate-permuted recurrent weights
    float* c_out[2];       // final cell-state dump [B*H]
};

__global__ __launch_bounds__(256) void lstm_scan(ScanArgs a)
{
    const int blk  = blockIdx.x;
    const int dir  = blk >> 6;
    const int col0 = (blk & 63) * 64;
    const int tid  = threadIdx.x;
    const int lane = tid & 31;
    const int warp = tid >> 5;
    const int mw   = warp & 3;
    const int nw   = warp >> 2;
    const int lq   = lane & 3;
    const int lr   = lane >> 2;

    const float* Zb0 = a.z[dir];
    const long   zss = a.z_ss[dir];
    float*       Hb  = a.h[dir];
    const long   hss = a.h_ss[dir];
    const long   hbs = a.h_bs[dir];
    const float* U   = a.U[dir];
    float*       hT  = g_hT + (long)dir * (2*HB);   // ping-pong pair for this dir

    __shared__ float As[2][32][72];   // [buf][k][b]
    __shared__ float Bs[2][32][68];   // [buf][k][n]

    // cp.async copy coordinates: thread owns rows vk and vk+16 of both tiles
    const int vk  = tid >> 4;         // 0..15
    const int vb4 = (tid & 15) * 4;   // 0..60
    uint32_t dstA[2][2], dstB[2][2];
    #pragma unroll
    for (int bu = 0; bu < 2; bu++) {
        dstA[bu][0] = (uint32_t)__cvta_generic_to_shared(&As[bu][vk][vb4]);
        dstA[bu][1] = (uint32_t)__cvta_generic_to_shared(&As[bu][vk+16][vb4]);
        dstB[bu][0] = (uint32_t)__cvta_generic_to_shared(&Bs[bu][vk][vb4]);
        dstB[bu][1] = (uint32_t)__cvta_generic_to_shared(&Bs[bu][vk+16][vb4]);
    }

    // register-resident cell state for this thread's 4 (b,j) pairs
    float creg[4] = {0.f, 0.f, 0.f, 0.f};
    const int jbase = ((col0 >> 5) + nw) * 8;

    for (int s = 0; s < TT; ++s) {
        const float* Z = Zb0 + (long)s * zss;

        float acc[4][4];
        #pragma unroll
        for (int g = 0; g < 4; g++)
            #pragma unroll
            for (int v = 0; v < 4; v++) acc[g][v] = 0.f;

        if (s > 0) {
            const float* hTp = hT + (long)((s - 1) & 1) * HB;  // h_T(s-1)

            // prologue: issue chunk 0 into buf 0
            cp16(dstA[0][0], hTp + (long)vk * 64 + vb4);
            cp16(dstA[0][1], hTp + (long)(vk + 16) * 64 + vb4);
            cp16(dstB[0][0], U + (long)vk * NG + col0 + vb4);
            cp16(dstB[0][1], U + (long)(vk + 16) * NG + col0 + vb4);
            cp_commit();

            int buf = 0;
            for (int k0 = 0; k0 < HH; k0 += 32) {
                cp_wait0();
                __syncthreads();
                if (k0 + 32 < HH) {
                    const int kn = k0 + 32;
                    const int nb = buf ^ 1;
                    cp16(dstA[nb][0], hTp + (long)(kn + vk) * 64 + vb4);
                    cp16(dstA[nb][1], hTp + (long)(kn + vk + 16) * 64 + vb4);
                    cp16(dstB[nb][0], U + (long)(kn + vk) * NG + col0 + vb4);
                    cp16(dstB[nb][1], U + (long)(kn + vk + 16) * NG + col0 + vb4);
                    cp_commit();
                }

                #pragma unroll
                for (int kk = 0; kk < 32; kk += 8) {
                    int r = mw*16 + lr;
                    float a0 = As[buf][kk + lq][r];
                    float a1 = As[buf][kk + lq][r + 8];
                    float a2 = As[buf][kk + 4 + lq][r];
                    float a3 = As[buf][kk + 4 + lq][r + 8];
                    #pragma unroll
                    for (int g = 0; g < 4; g++) {
                        int cb = nw*32 + g*8 + lr;
                        float b0 = Bs[buf][kk + lq][cb];
                        float b1 = Bs[buf][kk + 4 + lq][cb];
                        mma_tf32(acc[g][0], acc[g][1], acc[g][2], acc[g][3],
                                 a0, a1, a2, a3, b0, b1);
                    }
                }
                buf ^= 1;
            }
        }

        // Gate epilogue; c in registers; h -> natural layout + rounded h_T
        float* ho  = Hb + (long)s * hss;
        float* hTc = hT + (long)(s & 1) * HB;
        #pragma unroll
        for (int r2 = 0; r2 < 2; r2++) {
            const int b = mw*16 + lr + 8*r2;
            const float* zrow = Z + (long)b * NG + col0 + nw*32;
            #pragma unroll
            for (int jj = 0; jj < 2; jj++) {
                const int v  = r2*2 + jj;
                const int zc = 2*lq + jj;
                float zi = acc[0][v] + zrow[zc];
                float zf = acc[1][v] + zrow[8 + zc];
                float zg = acc[2][v] + zrow[16 + zc];
                float zo = acc[3][v] + zrow[24 + zc];
                float si = 1.f / (1.f + __expf(-zi));
                float sf = 1.f / (1.f + __expf(-zf));
                float so = 1.f / (1.f + __expf(-zo));
                float cn = sf * creg[v] + si * tanhf(zg);
                float hn = so * tanhf(cn);
                creg[v] = cn;
                const int j = jbase + zc;
                ho[(long)b * hbs + j] = hn;
                hTc[(long)j * 64 + b] = f2tf(hn);
            }
        }

        // -------- grid barrier (release h(s)/h_T(s) to all blocks) --------
        __syncthreads();
        if (tid == 0) {
            __threadfence();
            atomicAdd(&g_bar, 1u);
            const unsigned target = (unsigned)(s + 1) * NBLK;
            unsigned v;
            do {
                asm volatile("ld.acquire.gpu.global.u32 %0, [%1];"
                             : "=r"(v) : "l"(&g_bar));
                if (v < target) __nanosleep(64);
            } while (v < target);
        }
        __syncthreads();
    }

    // dump final cell state
    float* cdst = a.c_out[dir];
    #pragma unroll
    for (int r2 = 0; r2 < 2; r2++) {
        const int b = mw*16 + lr + 8*r2;
        #pragma unroll
        for (int jj = 0; jj < 2; jj++) {
            const int v  = r2*2 + jj;
            const int zc = 2*lq + jj;
            cdst[b * HH + (jbase + zc)] = creg[v];
        }
    }
}

// ---------------------------------------------------------------------------
// Final-state tail: [h_f0, c_f0, h_f1, c_f1], each [B,H].
// ---------------------------------------------------------------------------
__global__ __launch_bounds__(256) void finalize(
    float* __restrict__ out, const float* __restrict__ h_f0_last,
    const float* __restrict__ c_f0, const float* __restrict__ c_f1)
{
    int idx = blockIdx.x * 256 + threadIdx.x;
    if (idx >= BB * HH) return;
    int b = idx >> 10;
    int j = idx & (HH - 1);
    float* tail = out + (long)BB * TT * OUT_STRIDE_T;
    tail[idx]           = h_f0_last[idx];
    tail[BB*HH + idx]   = c_f0[idx];
    tail[2*BB*HH + idx] = out[(long)b * OUT_STRIDE_B + 127 * OUT_STRIDE_T + j];
    tail[3*BB*HH + idx] = c_f1[idx];
}

// ---------------------------------------------------------------------------
// Host launch
// ---------------------------------------------------------------------------
static float* dev_addr(const void* sym) {
    void* p = nullptr;
    cudaGetSymbolAddress(&p, sym);
    return (float*)p;
}

extern "C" void kernel_launch(void* const* d_in, const int* in_sizes, int n_in,
                              void* d_out, int out_size)
{
    (void)in_sizes; (void)n_in; (void)out_size;
    const int*   tokens = (const int*)  d_in[0];
    const float* emb    = (const float*)d_in[1];
    const float* W_f0   = (const float*)d_in[2];
    const float* U_f0   = (const float*)d_in[3];
    const float* b_f0   = (const float*)d_in[4];
    const float* W_f1   = (const float*)d_in[5];
    const float* U_f1   = (const float*)d_in[6];
    const float* b_f1   = (const float*)d_in[7];
    const float* W_b0   = (const float*)d_in[8];
    const float* U_b0   = (const float*)d_in[9];
    const float* b_b0   = (const float*)d_in[10];
    const float* W_b1   = (const float*)d_in[11];
    const float* U_b1   = (const float*)d_in[12];
    const float* b_b1   = (const float*)d_in[13];
    float* out = (float*)d_out;

    static float *X=nullptr, *Zf, *Zb, *H0f, *H0b,
                 *Wp_f0, *Wp_b0, *Wp_f1, *Wp_b1,
                 *Up_f0, *Up_b0, *Up_f1, *Up_b1,
                 *c_f0, *c_b0, *c_f1, *c_b1;
    static void* bar_addr = nullptr;
    if (!X) {
        X   = dev_addr(g_X);   Zf  = dev_addr(g_Zf);  Zb  = dev_addr(g_Zb);
        H0f = dev_addr(g_H0f); H0b = dev_addr(g_H0b);
        Wp_f0 = dev_addr(g_Wp_f0); Wp_b0 = dev_addr(g_Wp_b0);
        Wp_f1 = dev_addr(g_Wp_f1); Wp_b1 = dev_addr(g_Wp_b1);
        Up_f0 = dev_addr(g_Up_f0); Up_b0 = dev_addr(g_Up_b0);
        Up_f1 = dev_addr(g_Up_f1); Up_b1 = dev_addr(g_Up_b1);
        c_f0 = dev_addr(g_c_f0); c_b0 = dev_addr(g_c_b0);
        c_f1 = dev_addr(g_c_f1); c_b1 = dev_addr(g_c_b1);
        cudaGetSymbolAddress(&bar_addr, g_bar);
    }

    // 1) embedding gather
    gather_embed<<<(TT*BB*EE + 255)/256, 256>>>(tokens, emb, X);

    // 2) gate-permute + tf32-round weights
    permute_w<<<(EE*NG + 255)/256, 256>>>(W_f0, Wp_f0, EE);
    permute_w<<<(EE*NG + 255)/256, 256>>>(W_b0, Wp_b0, EE);
    permute_w<<<(HH*NG + 255)/256, 256>>>(W_f1, Wp_f1, HH);
    permute_w<<<(HH*NG + 255)/256, 256>>>(W_b1, Wp_b1, HH);
    permute_w<<<(HH*NG + 255)/256, 256>>>(U_f0, Up_f0, HH);
    permute_w<<<(HH*NG + 255)/256, 256>>>(U_b0, Up_b0, HH);
    permute_w<<<(HH*NG + 255)/256, 256>>>(U_f1, Up_f1, HH);
    permute_w<<<(HH*NG + 255)/256, 256>>>(U_b1, Up_b1, HH);

    // 3) layer-0 input projections
    {
        dim3 grid(NG/128, (TT*BB)/128);
        gemm_tf32_bias<<<grid, 256>>>(X, Wp_f0, b_f0, Zf, TT*BB, EE);
        gemm_tf32_bias<<<grid, 256>>>(X, Wp_b0, b_b0, Zb, TT*BB, EE);
    }

    // 4) layer-0 persistent scan
    {
        cudaMemsetAsync(bar_addr, 0, sizeof(unsigned));
        ScanArgs a;
        a.z[0] = Zf;                        a.z_ss[0] = (long)BB * NG;
        a.z[1] = Zb + 127L * BB * NG;       a.z_ss[1] = -(long)BB * NG;
        a.h[0] = H0f;  a.h_ss[0] = (long)BB * HH;  a.h_bs[0] = HH;
        a.h[1] = H0b;  a.h_ss[1] = (long)BB * HH;  a.h_bs[1] = HH;
        a.U[0] = Up_f0;  a.U[1] = Up_b0;
        a.c_out[0] = c_f0;  a.c_out[1] = c_b0;
        lstm_scan<<<NBLK, 256>>>(a);
    }

    // 5) layer-1 input projections
    {
        dim3 grid(NG/128, (TT*BB)/128);
        gemm_tf32_bias<<<grid, 256>>>(H0f, Wp_f1, b_f1, Zf, TT*BB, HH);
        gemm_tf32_bias<<<grid, 256>>>(H0b, Wp_b1, b_b1, Zb, TT*BB, HH);
    }

    // 6) layer-1 persistent scan; h written directly into d_out [B,T,2H]
    {
        cudaMemsetAsync(bar_addr, 0, sizeof(unsigned));
        ScanArgs a;
        a.z[0] = Zf;  a.z_ss[0] = (long)BB * NG;
        a.z[1] = Zb;  a.z_ss[1] = (long)BB * NG;   // L1 bwd Z already in scan order
        a.h[0] = out;                       a.h_ss[0] = OUT_STRIDE_T;
        a.h[1] = out + 127L*OUT_STRIDE_T + HH;  a.h_ss[1] = -(long)OUT_STRIDE_T;
        a.h_bs[0] = OUT_STRIDE_B;  a.h_bs[1] = OUT_STRIDE_B;
        a.U[0] = Up_f1;  a.U[1] = Up_b1;
        a.c_out[0] = c_f1;  a.c_out[1] = c_b1;
        lstm_scan<<<NBLK, 256>>>(a);
    }

    // 7) final states tail
    finalize<<<(BB*HH + 255)/256, 256>>>(
        out, H0f + (long)(TT-1) * BB * HH, c_f0, c_f1);
}